// round 13
// baseline (speedup 1.0000x reference)
#include <cuda_runtime.h>
#include <cuda_fp16.h>
#include <math.h>
#include <stdint.h>

#define NN 8192
#define DD 512
#define NT 64            // 8192 / 128 tiles per dim
#define CHUNKS 8         // K chunks of 64 fp16 (128B)
#define ROWB 1024        // bytes per packed fp16 row (512 * 2)

// fp16 copy of X (contiguous row-major), filled by prep_kernel each call
__device__ __align__(128) __half g_P[(size_t)NN * DD];
// softplus variance per row (applied to cov diagonal by diag GEMM tiles)
__device__ float g_diag[NN];

// ---------------- helpers ----------------
__device__ __forceinline__ uint32_t smem_u32(const void* p) {
    uint32_t a;
    asm("{ .reg .u64 t; cvta.to.shared.u64 t, %1; cvt.u32.u64 %0, t; }"
        : "=r"(a) : "l"(p));
    return a;
}
__device__ __forceinline__ void cp_async16(uint32_t sa, const void* ga) {
    asm volatile("cp.async.cg.shared.global [%0], [%1], 16;" :: "r"(sa), "l"(ga));
}
#define CP_COMMIT() asm volatile("cp.async.commit_group;" ::: "memory")
#define CP_WAIT(n)  asm volatile("cp.async.wait_group %0;" :: "n"(n) : "memory")

#define LDSM4(r0, r1, r2, r3, ad) \
    asm volatile("ldmatrix.sync.aligned.m8n8.x4.shared.b16 {%0,%1,%2,%3}, [%4];" \
                 : "=r"(r0), "=r"(r1), "=r"(r2), "=r"(r3) : "r"(ad))

// f16-accumulator HMMA: D(f16x2 pair) = A*B + D
#define MMA_F16ACC(d, a, b) \
    asm volatile("mma.sync.aligned.m16n8k16.row.col.f16.f16.f16.f16 " \
                 "{%0,%1}, {%2,%3,%4,%5}, {%6,%7}, {%0,%1};" \
                 : "+r"((d)[0]), "+r"((d)[1]) \
                 : "r"((a)[0]), "r"((a)[1]), "r"((a)[2]), "r"((a)[3]), \
                   "r"((b)[0]), "r"((b)[1]))

// f16-accumulator HMMA with C = 0 (starts a fresh chunk accumulation)
#define MMA_F16ZERO(d, a, b) \
    asm volatile("mma.sync.aligned.m16n8k16.row.col.f16.f16.f16.f16 " \
                 "{%0,%1}, {%2,%3,%4,%5}, {%6,%7}, {%8,%8};" \
                 : "=r"((d)[0]), "=r"((d)[1]) \
                 : "r"((a)[0]), "r"((a)[1]), "r"((a)[2]), "r"((a)[3]), \
                   "r"((b)[0]), "r"((b)[1]), "r"(0u))

// ---------------- fused pre-pass ----------------
__global__ void __launch_bounds__(256)
prep_kernel(const float* __restrict__ X,
            const float* __restrict__ muK,
            const float* __restrict__ varK,
            const float* __restrict__ muB,
            const float* __restrict__ varB,
            float* __restrict__ outMu)
{
    const int row  = blockIdx.x * 8 + (threadIdx.x >> 5);
    const int lane = threadIdx.x & 31;

    const float* xr = X + (size_t)row * DD;
    char* prow = (char*)g_P + (size_t)row * ROWB;

    float smu = 0.0f, sv = 0.0f;
#pragma unroll
    for (int j = 0; j < 4; j++) {
        const int k = lane * 4 + j * 128;
        const float4 xv = *(const float4*)(xr + k);
        const float4 m  = *(const float4*)(muK + k);
        const float4 v  = *(const float4*)(varK + k);
        smu = fmaf(xv.x, m.x, smu); smu = fmaf(xv.y, m.y, smu);
        smu = fmaf(xv.z, m.z, smu); smu = fmaf(xv.w, m.w, smu);
        sv  = fmaf(xv.x, v.x, sv);  sv  = fmaf(xv.y, v.y, sv);
        sv  = fmaf(xv.z, v.z, sv);  sv  = fmaf(xv.w, v.w, sv);

        __half2 p0 = __floats2half2_rn(xv.x, xv.y);
        __half2 p1 = __floats2half2_rn(xv.z, xv.w);
        uint2 w;
        w.x = *(uint32_t*)&p0;
        w.y = *(uint32_t*)&p1;
        *(uint2*)(prow + k * 2) = w;
    }
#pragma unroll
    for (int o = 16; o; o >>= 1) {
        smu += __shfl_xor_sync(0xFFFFFFFFu, smu, o);
        sv  += __shfl_xor_sync(0xFFFFFFFFu, sv, o);
    }
    if (lane == 0) {
        outMu[row] = smu + __ldg(muB);
        const float z = sv + __ldg(varB);
        g_diag[row] = log1pf(expf(z)) + 1e-8f;
    }
}

// ---------------- symmetric fp16 HMMA GEMM (f16 accumulate per chunk) ----------------
// 128x128 CTA tile, 4 warps (2x2) of 64x64. Per K=64 chunk: accumulate the
// 4 ks-steps in f16 accumulators, then promote once into fp32 registers.
#define STAGE_BYTES 32768
#define NSTAGE 3
#define SMEM_BYTES  (1024 + NSTAGE * STAGE_BYTES)   // 99328
#define EPIT 132              // epilogue stage pitch (floats)

__global__ void __launch_bounds__(128, 2)
xxt_hmma_kernel(const float* __restrict__ rho_k, float* __restrict__ C)
{
    const int tileC = blockIdx.x;
    const int tileR = blockIdx.y;
    if (tileC < tileR) return;
    const bool diag = (tileC == tileR);

    extern __shared__ char sm_raw[];
    const uint32_t raw  = smem_u32(sm_raw);
    const uint32_t base = (raw + 1023) & ~1023u;

    const int tid  = threadIdx.x;
    const int lane = tid & 31;
    const int warp = tid >> 5;
    const int wr   = warp >> 1;   // 0..1
    const int wc   = warp & 1;    // 0..1
    const int hl   = lane >> 4;   // ldmatrix column-half select
    const int l15  = lane & 15;

    const int R0 = tileR * 128;
    const int C0 = tileC * 128;

    float acc[4][8][4];
#pragma unroll
    for (int i = 0; i < 4; i++)
#pragma unroll
        for (int j = 0; j < 8; j++)
#pragma unroll
            for (int k = 0; k < 4; k++) acc[i][j][k] = 0.0f;

    const char* gp = (const char*)g_P;

    // hoisted per-warp fragment row info
    int rowOffA[4], r7A[4], rowOffB[4], r7B[4];
#pragma unroll
    for (int i = 0; i < 4; i++) {
        const int ra = wr * 64 + i * 16 + l15;
        const int rb = wc * 64 + i * 16 + l15;
        rowOffA[i] = ra * 128; r7A[i] = ra & 7;
        rowOffB[i] = rb * 128; r7B[i] = rb & 7;
    }

#define LOAD_CHUNK(cc, ss)                                                     \
    do {                                                                       \
        const uint32_t sb = base + (ss) * STAGE_BYTES;                         \
        _Pragma("unroll")                                                      \
        for (int i = 0; i < 8; i++) {                                          \
            const int idx  = i * 128 + tid;                                    \
            const int row  = idx >> 3;                                         \
            const int unit = idx & 7;                                          \
            const uint32_t so =                                                \
                (uint32_t)(row * 128 + ((unit ^ (row & 7)) << 4));             \
            cp_async16(sb + so,                                                \
                       gp + (size_t)(R0 + row) * ROWB + (cc) * 128 + unit*16); \
            if (!diag)                                                         \
                cp_async16(sb + 16384 + so,                                    \
                           gp + (size_t)(C0 + row) * ROWB + (cc)*128 + unit*16);\
        }                                                                      \
        CP_COMMIT();                                                           \
    } while (0)

    LOAD_CHUNK(0, 0);
    LOAD_CHUNK(1, 1);

#pragma unroll
    for (int c = 0; c < CHUNKS; c++) {
        if (c + 2 < CHUNKS) { CP_WAIT(1); } else { CP_WAIT(0); }
        __syncthreads();   // stage c visible; stage c-1 free to overwrite

        if (c + 2 < CHUNKS) LOAD_CHUNK(c + 2, (c + 2) % NSTAGE);

        const uint32_t bA = base + (c % NSTAGE) * STAGE_BYTES;
        const uint32_t bB = diag ? bA : (bA + 16384);

        uint32_t hAcc[4][8][2];   // f16x2 accumulators for this chunk

#pragma unroll
        for (int ks = 0; ks < 4; ks++) {
            const int u = ks * 2 + hl;
            uint32_t aF[4][4], bF[8][2];

            // A fragments
#pragma unroll
            for (int mi = 0; mi < 4; mi++) {
                const uint32_t ad = bA + rowOffA[mi] + ((u ^ r7A[mi]) << 4);
                LDSM4(aF[mi][0], aF[mi][1], aF[mi][2], aF[mi][3], ad);
            }
            // B fragments
#pragma unroll
            for (int bj = 0; bj < 4; bj++) {
                const uint32_t ad = bB + rowOffB[bj] + ((u ^ r7B[bj]) << 4);
                uint32_t t0, t1, t2, t3;
                LDSM4(t0, t1, t2, t3, ad);
                bF[2 * bj][0] = t0; bF[2 * bj + 1][0] = t1;
                bF[2 * bj][1] = t2; bF[2 * bj + 1][1] = t3;
            }

            if (ks == 0) {
#pragma unroll
                for (int mi = 0; mi < 4; mi++)
#pragma unroll
                    for (int nj = 0; nj < 8; nj++)
                        MMA_F16ZERO(hAcc[mi][nj], aF[mi], bF[nj]);
            } else {
#pragma unroll
                for (int mi = 0; mi < 4; mi++)
#pragma unroll
                    for (int nj = 0; nj < 8; nj++)
                        MMA_F16ACC(hAcc[mi][nj], aF[mi], bF[nj]);
            }
        }

        // promote chunk result (f16) into fp32 accumulators
#pragma unroll
        for (int mi = 0; mi < 4; mi++) {
#pragma unroll
            for (int nj = 0; nj < 8; nj++) {
                __half2 p0 = *reinterpret_cast<__half2*>(&hAcc[mi][nj][0]);
                __half2 p1 = *reinterpret_cast<__half2*>(&hAcc[mi][nj][1]);
                acc[mi][nj][0] += __low2float(p0);
                acc[mi][nj][1] += __high2float(p0);
                acc[mi][nj][2] += __low2float(p1);
                acc[mi][nj][3] += __high2float(p1);
            }
        }
    }

    // ---------------- epilogue ----------------
    const float s = __ldg(rho_k);

    // Upper tile: direct register stores
#pragma unroll
    for (int mi = 0; mi < 4; mi++) {
#pragma unroll
        for (int nj = 0; nj < 8; nj++) {
            const int row = R0 + wr * 64 + mi * 16 + (lane >> 2);
            const int col = C0 + wc * 64 + nj * 8 + (lane & 3) * 2;
            float2 v0 = make_float2(acc[mi][nj][0] * s, acc[mi][nj][1] * s);
            float2 v1 = make_float2(acc[mi][nj][2] * s, acc[mi][nj][3] * s);
            *(float2*)&C[(size_t)row * NN + col]       = v0;
            *(float2*)&C[(size_t)(row + 8) * NN + col] = v1;
        }
    }

    if (diag) {
        // patch the covariance diagonal with the softplus variance
        __syncthreads();   // order vs the float2 stores above (CTA scope)
        const int r = R0 + tid;
        C[(size_t)r * NN + r] = g_diag[r];
    } else {
        // Mirror tile (transposed) via full-tile smem staging
        float* stage = (float*)(sm_raw + (base - raw));
        __syncthreads();   // all warps done reading pipeline smem
#pragma unroll
        for (int mi = 0; mi < 4; mi++) {
#pragma unroll
            for (int nj = 0; nj < 8; nj++) {
                const int r   = wr * 64 + mi * 16 + (lane >> 2);
                const int col = wc * 64 + nj * 8 + (lane & 3) * 2;
                float2 v0 = make_float2(acc[mi][nj][0] * s, acc[mi][nj][1] * s);
                float2 v1 = make_float2(acc[mi][nj][2] * s, acc[mi][nj][3] * s);
                *(float2*)&stage[(size_t)r * EPIT + col]       = v0;
                *(float2*)&stage[(size_t)(r + 8) * EPIT + col] = v1;
            }
        }
        __syncthreads();
        const int m = tid;  // mirror row = tile col
#pragma unroll 8
        for (int j = 0; j < 128; j += 4) {
            float4 v;
            v.x = stage[(size_t)(j + 0) * EPIT + m];
            v.y = stage[(size_t)(j + 1) * EPIT + m];
            v.z = stage[(size_t)(j + 2) * EPIT + m];
            v.w = stage[(size_t)(j + 3) * EPIT + m];
            *(float4*)&C[(size_t)(C0 + m) * NN + R0 + j] = v;
        }
    }
}

extern "C" void kernel_launch(void* const* d_in, const int* in_sizes, int n_in,
                              void* d_out, int out_size)
{
    const float* x     = (const float*)d_in[0];
    const float* mu_k  = (const float*)d_in[1];
    const float* rho_k = (const float*)d_in[2];
    const float* var_k = (const float*)d_in[3];
    const float* mu_b  = (const float*)d_in[4];
    const float* var_b = (const float*)d_in[5];

    float* out_mu = (float*)d_out;
    float* cov    = out_mu + NN;

    cudaFuncSetAttribute(xxt_hmma_kernel,
                         cudaFuncAttributeMaxDynamicSharedMemorySize, SMEM_BYTES);

    prep_kernel<<<NN / 8, 256>>>(x, mu_k, var_k, mu_b, var_b, out_mu);
    xxt_hmma_kernel<<<dim3(NT, NT), 128, SMEM_BYTES>>>(rho_k, cov);
}

// round 14
// speedup vs baseline: 1.9360x; 1.9360x over previous
#include <cuda_runtime.h>
#include <cuda_fp16.h>
#include <math.h>
#include <stdint.h>

#define NN 8192
#define DD 512
#define NT 64            // 8192 / 128 tiles per dim
#define CHUNKS 8         // K chunks of 64 fp16 (128B)
#define ROWB 1024        // bytes per packed fp16 row (512 * 2)

// fp16 copy of X (contiguous row-major), filled by prep_kernel each call
__device__ __align__(128) __half g_P[(size_t)NN * DD];
// softplus variance per row (applied to cov diagonal by diag GEMM tiles)
__device__ float g_diag[NN];

// ---------------- helpers ----------------
__device__ __forceinline__ uint32_t smem_u32(const void* p) {
    uint32_t a;
    asm("{ .reg .u64 t; cvta.to.shared.u64 t, %1; cvt.u32.u64 %0, t; }"
        : "=r"(a) : "l"(p));
    return a;
}
__device__ __forceinline__ void cp_async16(uint32_t sa, const void* ga) {
    asm volatile("cp.async.cg.shared.global [%0], [%1], 16;" :: "r"(sa), "l"(ga));
}
#define CP_COMMIT() asm volatile("cp.async.commit_group;" ::: "memory")
#define CP_WAIT(n)  asm volatile("cp.async.wait_group %0;" :: "n"(n) : "memory")

#define LDSM4(r0, r1, r2, r3, ad) \
    asm volatile("ldmatrix.sync.aligned.m8n8.x4.shared.b16 {%0,%1,%2,%3}, [%4];" \
                 : "=r"(r0), "=r"(r1), "=r"(r2), "=r"(r3) : "r"(ad))

#define MMA_F16(d, a, b) \
    asm volatile("mma.sync.aligned.m16n8k16.row.col.f32.f16.f16.f32 " \
                 "{%0,%1,%2,%3}, {%4,%5,%6,%7}, {%8,%9}, {%0,%1,%2,%3};" \
                 : "+f"((d)[0]), "+f"((d)[1]), "+f"((d)[2]), "+f"((d)[3]) \
                 : "r"((a)[0]), "r"((a)[1]), "r"((a)[2]), "r"((a)[3]), \
                   "r"((b)[0]), "r"((b)[1]))

// ---------------- fused pre-pass ----------------
__global__ void __launch_bounds__(256)
prep_kernel(const float* __restrict__ X,
            const float* __restrict__ muK,
            const float* __restrict__ varK,
            const float* __restrict__ muB,
            const float* __restrict__ varB,
            float* __restrict__ outMu)
{
    const int row  = blockIdx.x * 8 + (threadIdx.x >> 5);
    const int lane = threadIdx.x & 31;

    const float* xr = X + (size_t)row * DD;
    char* prow = (char*)g_P + (size_t)row * ROWB;

    float smu = 0.0f, sv = 0.0f;
#pragma unroll
    for (int j = 0; j < 4; j++) {
        const int k = lane * 4 + j * 128;
        const float4 xv = *(const float4*)(xr + k);
        const float4 m  = *(const float4*)(muK + k);
        const float4 v  = *(const float4*)(varK + k);
        smu = fmaf(xv.x, m.x, smu); smu = fmaf(xv.y, m.y, smu);
        smu = fmaf(xv.z, m.z, smu); smu = fmaf(xv.w, m.w, smu);
        sv  = fmaf(xv.x, v.x, sv);  sv  = fmaf(xv.y, v.y, sv);
        sv  = fmaf(xv.z, v.z, sv);  sv  = fmaf(xv.w, v.w, sv);

        __half2 p0 = __floats2half2_rn(xv.x, xv.y);
        __half2 p1 = __floats2half2_rn(xv.z, xv.w);
        uint2 w;
        w.x = *(uint32_t*)&p0;
        w.y = *(uint32_t*)&p1;
        *(uint2*)(prow + k * 2) = w;
    }
#pragma unroll
    for (int o = 16; o; o >>= 1) {
        smu += __shfl_xor_sync(0xFFFFFFFFu, smu, o);
        sv  += __shfl_xor_sync(0xFFFFFFFFu, sv, o);
    }
    if (lane == 0) {
        outMu[row] = smu + __ldg(muB);
        const float z = sv + __ldg(varB);
        g_diag[row] = log1pf(expf(z)) + 1e-8f;
    }
}

// ---------------- symmetric fp16 HMMA GEMM ----------------
// 128x128 CTA tile, 4 warps (2x2) of 64x64 each, fully unrolled chunk loop.
// Epilogue: fully coalesced row stores via smem staging (two passes).
#define STAGE_BYTES 32768
#define NSTAGE 3
#define SMEM_BYTES  (1024 + NSTAGE * STAGE_BYTES)   // 99328
#define EPIT 132              // epilogue stage pitch (floats); %4==0 for LDS.128

__global__ void __launch_bounds__(128, 2)
xxt_hmma_kernel(const float* __restrict__ rho_k, float* __restrict__ C)
{
    const int tileC = blockIdx.x;
    const int tileR = blockIdx.y;
    if (tileC < tileR) return;
    const bool diag = (tileC == tileR);

    extern __shared__ char sm_raw[];
    const uint32_t raw  = smem_u32(sm_raw);
    const uint32_t base = (raw + 1023) & ~1023u;

    const int tid  = threadIdx.x;
    const int lane = tid & 31;
    const int warp = tid >> 5;
    const int wr   = warp >> 1;   // 0..1
    const int wc   = warp & 1;    // 0..1
    const int hl   = lane >> 4;   // ldmatrix column-half select
    const int l15  = lane & 15;

    // CTA-dependent phase offset so co-resident CTAs de-correlate
    const int skew = (tileC + tileR) & 3;

    const int R0 = tileR * 128;
    const int C0 = tileC * 128;

    float acc[4][8][4];
#pragma unroll
    for (int i = 0; i < 4; i++)
#pragma unroll
        for (int j = 0; j < 8; j++)
#pragma unroll
            for (int k = 0; k < 4; k++) acc[i][j][k] = 0.0f;

    const char* gp = (const char*)g_P;

    // hoisted per-warp fragment row info
    int rowOffA[4], r7A[4], rowOffB[4], r7B[4];
#pragma unroll
    for (int i = 0; i < 4; i++) {
        const int ra = wr * 64 + i * 16 + l15;
        const int rb = wc * 64 + i * 16 + l15;
        rowOffA[i] = ra * 128; r7A[i] = ra & 7;
        rowOffB[i] = rb * 128; r7B[i] = rb & 7;
    }

#define LOAD_CHUNK(cc, ss)                                                     \
    do {                                                                       \
        const uint32_t sb = base + (ss) * STAGE_BYTES;                         \
        _Pragma("unroll")                                                      \
        for (int i = 0; i < 8; i++) {                                          \
            const int idx  = i * 128 + tid;                                    \
            const int row  = idx >> 3;                                         \
            const int unit = idx & 7;                                          \
            const uint32_t so =                                                \
                (uint32_t)(row * 128 + ((unit ^ (row & 7)) << 4));             \
            cp_async16(sb + so,                                                \
                       gp + (size_t)(R0 + row) * ROWB + (cc) * 128 + unit*16); \
            if (!diag)                                                         \
                cp_async16(sb + 16384 + so,                                    \
                           gp + (size_t)(C0 + row) * ROWB + (cc)*128 + unit*16);\
        }                                                                      \
        CP_COMMIT();                                                           \
    } while (0)

    LOAD_CHUNK(0, 0);
    LOAD_CHUNK(1, 1);

#pragma unroll
    for (int c = 0; c < CHUNKS; c++) {
        if (c + 2 < CHUNKS) { CP_WAIT(1); } else { CP_WAIT(0); }
        __syncthreads();   // stage c visible; stage c-1 free to overwrite

        if (c + 2 < CHUNKS) LOAD_CHUNK(c + 2, (c + 2) % NSTAGE);

        const uint32_t bA = base + (c % NSTAGE) * STAGE_BYTES;
        const uint32_t bB = diag ? bA : (bA + 16384);

#pragma unroll
        for (int ksi = 0; ksi < 4; ksi++) {
            const int ks = (ksi + skew) & 3;
            const int u  = ks * 2 + hl;
            uint32_t aF[4][4], bF[8][2];

            // A fragments
#pragma unroll
            for (int mi = 0; mi < 4; mi++) {
                const uint32_t ad = bA + rowOffA[mi] + ((u ^ r7A[mi]) << 4);
                LDSM4(aF[mi][0], aF[mi][1], aF[mi][2], aF[mi][3], ad);
            }
            // B fragments
#pragma unroll
            for (int bj = 0; bj < 4; bj++) {
                const uint32_t ad = bB + rowOffB[bj] + ((u ^ r7B[bj]) << 4);
                uint32_t t0, t1, t2, t3;
                LDSM4(t0, t1, t2, t3, ad);
                bF[2 * bj][0] = t0; bF[2 * bj + 1][0] = t1;
                bF[2 * bj][1] = t2; bF[2 * bj + 1][1] = t3;
            }

#pragma unroll
            for (int mi = 0; mi < 4; mi++)
#pragma unroll
                for (int nj = 0; nj < 8; nj++)
                    MMA_F16(acc[mi][nj], aF[mi], bF[nj]);
        }
    }

    // ---------------- epilogue (fully coalesced via smem staging) ----------------
    const float s = __ldg(rho_k);
    float* stage = (float*)(sm_raw + (base - raw));

    // ---- pass 1: upper tile, direct layout ----
    __syncthreads();   // all mainloop smem reads done; stage may be overwritten
#pragma unroll
    for (int mi = 0; mi < 4; mi++) {
#pragma unroll
        for (int nj = 0; nj < 8; nj++) {
            const int r   = wr * 64 + mi * 16 + (lane >> 2);
            const int col = wc * 64 + nj * 8 + (lane & 3) * 2;
            float2 v0 = make_float2(acc[mi][nj][0] * s, acc[mi][nj][1] * s);
            float2 v1 = make_float2(acc[mi][nj][2] * s, acc[mi][nj][3] * s);
            *(float2*)&stage[(size_t)r * EPIT + col]       = v0;
            *(float2*)&stage[(size_t)(r + 8) * EPIT + col] = v1;
        }
    }
    __syncthreads();
    // coalesced row writes: warp w owns rows w*32..w*32+31; one 512B row per step
#pragma unroll 4
    for (int i = 0; i < 32; i++) {
        const int row = warp * 32 + i;
        float4 v = *(float4*)&stage[(size_t)row * EPIT + lane * 4];
        *(float4*)&C[(size_t)(R0 + row) * NN + C0 + lane * 4] = v;
    }

    if (diag) {
        // patch the covariance diagonal with the softplus variance
        __syncthreads();   // order vs the row stores above (CTA scope)
        const int r = R0 + tid;
        C[(size_t)r * NN + r] = g_diag[r];
    } else {
        // ---- pass 2: mirror tile, transposed layout ----
        __syncthreads();   // pass-1 reads done
#pragma unroll
        for (int mi = 0; mi < 4; mi++) {
#pragma unroll
            for (int nj = 0; nj < 8; nj++) {
                const int r = wr * 64 + mi * 16 + (lane >> 2);
                const int c0 = wc * 64 + nj * 8 + (lane & 3) * 2;
                // transposed: stage[col][row]; STS.32, conflict-free banks
                stage[(size_t)(c0 + 0) * EPIT + r]     = acc[mi][nj][0] * s;
                stage[(size_t)(c0 + 1) * EPIT + r]     = acc[mi][nj][1] * s;
                stage[(size_t)(c0 + 0) * EPIT + r + 8] = acc[mi][nj][2] * s;
                stage[(size_t)(c0 + 1) * EPIT + r + 8] = acc[mi][nj][3] * s;
            }
        }
        __syncthreads();
        // coalesced mirror-row writes: mirror row m = tile column m
#pragma unroll 4
        for (int i = 0; i < 32; i++) {
            const int m = warp * 32 + i;
            float4 v = *(float4*)&stage[(size_t)m * EPIT + lane * 4];
            *(float4*)&C[(size_t)(C0 + m) * NN + R0 + lane * 4] = v;
        }
    }
}

extern "C" void kernel_launch(void* const* d_in, const int* in_sizes, int n_in,
                              void* d_out, int out_size)
{
    const float* x     = (const float*)d_in[0];
    const float* mu_k  = (const float*)d_in[1];
    const float* rho_k = (const float*)d_in[2];
    const float* var_k = (const float*)d_in[3];
    const float* mu_b  = (const float*)d_in[4];
    const float* var_b = (const float*)d_in[5];

    float* out_mu = (float*)d_out;
    float* cov    = out_mu + NN;

    cudaFuncSetAttribute(xxt_hmma_kernel,
                         cudaFuncAttributeMaxDynamicSharedMemorySize, SMEM_BYTES);

    prep_kernel<<<NN / 8, 256>>>(x, mu_k, var_k, mu_b, var_b, out_mu);
    xxt_hmma_kernel<<<dim3(NT, NT), 128, SMEM_BYTES>>>(rho_k, cov);
}